// round 2
// baseline (speedup 1.0000x reference)
#include <cuda_runtime.h>
#include <cuda_fp16.h>
#include <math.h>
#include <cstdint>

#define J 4
#define BATCH 8192
#define TIN 10
#define TOUT 10
#define HDIM 100
#define VDIM 11
#define JB (J*BATCH)

// ---------------- global scratch (allocation-free) ----------------
__device__ float  g_H [(size_t)JB*TIN*HDIM];   // [b][j][t][e] fp32
__device__ __half g_HA[(size_t)JB*TIN*HDIM];   // [b][j][t][f] fp16

__device__ __forceinline__ float sigm(float x){ return 1.0f/(1.0f+__expf(-x)); }

// =================================================================
// Encoder: 12 warps/block, 4 sequences/warp (48 seq/block)
// =================================================================
#define EWARPS 12
#define ESEQW 4
#define ESEQB (EWARPS*ESEQW)
#define ETHREADS (EWARPS*32)

// smem float offsets
#define E_WHH 0            // WhhT [100][300]
#define E_WIH 30000        // WihT [11][300]
#define E_AW  33300        // A_w  [100][100]
#define E_BIH 43300        // [300]
#define E_BHH 43600        // [300]
#define E_H   43900        // h [48][100]
#define E_FLOATS 48700     // 194800 bytes

__global__ void __launch_bounds__(ETHREADS,1)
enc_kernel(const int* __restrict__ inputs,
           const float* __restrict__ Wih, const float* __restrict__ Whh,
           const float* __restrict__ bih, const float* __restrict__ bhh,
           const float* __restrict__ Aw)
{
    extern __shared__ float sm[];
    const int tid = threadIdx.x;
    for (int i = tid; i < 300*100; i += ETHREADS){ int g=i/100,k=i%100; sm[E_WHH + k*300+g] = Whh[i]; }
    for (int i = tid; i < 300*11;  i += ETHREADS){ int g=i/11, v=i%11;  sm[E_WIH + v*300+g] = Wih[i]; }
    for (int i = tid; i < 100*100; i += ETHREADS) sm[E_AW+i] = Aw[i];
    for (int i = tid; i < 300;     i += ETHREADS){ sm[E_BIH+i]=bih[i]; sm[E_BHH+i]=bhh[i]; }
    __syncthreads();

    const int warp = tid>>5, lane = tid&31;
    const int s0 = blockIdx.x*ESEQB + warp*ESEQW;
    int jj[ESEQW], bb[ESEQW];
    float* hrow[ESEQW];
    #pragma unroll
    for (int i=0;i<ESEQW;i++){
        int s = min(s0+i, JB-1);
        jj[i]=s/BATCH; bb[i]=s-jj[i]*BATCH;
        hrow[i] = &sm[E_H + (warp*ESEQW+i)*HDIM];
    }
    #pragma unroll
    for (int m=0;m<4;m++){ int e=lane+32*m; if(e<HDIM){
        #pragma unroll
        for(int i=0;i<ESEQW;i++) hrow[i][e]=0.f; } }
    __syncwarp();

    for (int t=0;t<TIN;t++){
        int tok[ESEQW];
        #pragma unroll
        for(int i=0;i<ESEQW;i++) tok[i] = inputs[(jj[i]*TIN+t)*BATCH + bb[i]];

        float ar[ESEQW][4], az[ESEQW][4], an[ESEQW][4];
        #pragma unroll
        for (int m=0;m<4;m++){ int e=lane+32*m; if(e<HDIM){
            float br=sm[E_BHH+e], bz=sm[E_BHH+100+e], bn=sm[E_BHH+200+e];
            #pragma unroll
            for(int i=0;i<ESEQW;i++){ ar[i][m]=br; az[i][m]=bz; an[i][m]=bn; } } }

        #pragma unroll 2
        for (int k=0;k<HDIM;k++){
            float hk[ESEQW];
            #pragma unroll
            for(int i=0;i<ESEQW;i++) hk[i]=hrow[i][k];
            const float* wrow = &sm[E_WHH + k*300];
            #pragma unroll
            for (int m=0;m<4;m++){ int e=lane+32*m; if(e<HDIM){
                float wr=wrow[e], wz=wrow[100+e], wn=wrow[200+e];
                #pragma unroll
                for(int i=0;i<ESEQW;i++){
                    ar[i][m] = fmaf(wr,hk[i],ar[i][m]);
                    az[i][m] = fmaf(wz,hk[i],az[i][m]);
                    an[i][m] = fmaf(wn,hk[i],an[i][m]);
                } } }
        }
        // gates + update (compute into regs first)
        float hnew[ESEQW][4];
        #pragma unroll
        for (int m=0;m<4;m++){ int e=lane+32*m; if(e<HDIM){
            float bir=sm[E_BIH+e], biz=sm[E_BIH+100+e], bin=sm[E_BIH+200+e];
            #pragma unroll
            for(int i=0;i<ESEQW;i++){
                const float* wi = &sm[E_WIH + tok[i]*300];
                float r = sigm(wi[e]     + bir + ar[i][m]);
                float z = sigm(wi[100+e] + biz + az[i][m]);
                float n = tanhf(wi[200+e]+ bin + r*an[i][m]);
                hnew[i][m] = (1.f-z)*n + z*hrow[i][e];
            } } }
        __syncwarp();
        #pragma unroll
        for (int m=0;m<4;m++){ int e=lane+32*m; if(e<HDIM){
            #pragma unroll
            for(int i=0;i<ESEQW;i++){
                hrow[i][e]=hnew[i][m];
                g_H[(size_t)((bb[i]*J + jj[i])*TIN + t)*HDIM + e] = hnew[i][m];
            } } }
        __syncwarp();
        // HA = h @ A_w  (fp16 out)
        float ha[ESEQW][4];
        #pragma unroll
        for(int m=0;m<4;m++){
            #pragma unroll
            for(int i=0;i<ESEQW;i++) ha[i][m]=0.f; }
        #pragma unroll 2
        for (int e=0;e<HDIM;e++){
            float he[ESEQW];
            #pragma unroll
            for(int i=0;i<ESEQW;i++) he[i]=hrow[i][e];
            const float* arow = &sm[E_AW + e*HDIM];
            #pragma unroll
            for(int m=0;m<4;m++){ int f=lane+32*m; if(f<HDIM){
                float a=arow[f];
                #pragma unroll
                for(int i=0;i<ESEQW;i++) ha[i][m]=fmaf(he[i],a,ha[i][m]);
            } }
        }
        #pragma unroll
        for(int m=0;m<4;m++){ int f=lane+32*m; if(f<HDIM){
            #pragma unroll
            for(int i=0;i<ESEQW;i++)
                g_HA[(size_t)((bb[i]*J+jj[i])*TIN + t)*HDIM + f] = __float2half(ha[i][m]);
        } }
        __syncwarp();
    }
}

// =================================================================
// Decoder: 12 warps/block, 1 batch element per warp
// =================================================================
#define DWARPS 12
#define DTHREADS (DWARPS*32)

// smem float offsets
#define D_WHH 0        // WhhT [100][300]          30000
#define D_WIH 30000    // WihT [11][300]            3300
#define D_VW  33300    // V_w [11][100]             1100
#define D_BIH 34400    // 300
#define D_BHH 34700    // 300
#define D_WB  35000    // 100
#define D_VB  35100    // 11  (+1 pad)
#define D_PC  35112    // [12][4][200]  P|c         9600
#define D_SC  44712    // [12][40]                   480
#define D_WW2 45192    // half2 [200][50]          10000 float slots
#define D_FLOATS 55192 // 220768 bytes

__device__ __forceinline__ void dec_gru(const float* __restrict__ sm,
                                        float* __restrict__ pc,
                                        int lane, int tok)
{
    float gr[J][4], gz[J][4], gn[J][4];
    #pragma unroll
    for (int m=0;m<4;m++){ int e=lane+32*m; if(e<HDIM){
        float br=sm[D_BHH+e], bz=sm[D_BHH+100+e], bn=sm[D_BHH+200+e];
        #pragma unroll
        for(int j=0;j<J;j++){ gr[j][m]=br; gz[j][m]=bz; gn[j][m]=bn; } } }
    #pragma unroll 2
    for (int k=0;k<HDIM;k++){
        float c4[J];
        #pragma unroll
        for(int j=0;j<J;j++) c4[j]=pc[j*200+100+k];
        const float* wrow=&sm[D_WHH+k*300];
        #pragma unroll
        for (int m=0;m<4;m++){ int e=lane+32*m; if(e<HDIM){
            float wr=wrow[e], wz=wrow[100+e], wn=wrow[200+e];
            #pragma unroll
            for(int j=0;j<J;j++){
                gr[j][m]=fmaf(wr,c4[j],gr[j][m]);
                gz[j][m]=fmaf(wz,c4[j],gz[j][m]);
                gn[j][m]=fmaf(wn,c4[j],gn[j][m]);
            } } }
    }
    const float* wi=&sm[D_WIH+tok*300];
    #pragma unroll
    for (int m=0;m<4;m++){ int e=lane+32*m; if(e<HDIM){
        float ir=wi[e]+sm[D_BIH+e], iz=wi[100+e]+sm[D_BIH+100+e], in=wi[200+e]+sm[D_BIH+200+e];
        #pragma unroll
        for(int j=0;j<J;j++){
            float r=sigm(ir+gr[j][m]);
            float z=sigm(iz+gz[j][m]);
            float n=tanhf(in + r*gn[j][m]);
            float cj=pc[j*200+100+e];
            pc[j*200+e]=(1.f-z)*n + z*cj;
        } } }
    __syncwarp();
}

__global__ void __launch_bounds__(DTHREADS,1)
dec_kernel(const int* __restrict__ target,
           const float* __restrict__ Wih, const float* __restrict__ Whh,
           const float* __restrict__ bih, const float* __restrict__ bhh,
           const float* __restrict__ Ww,  const float* __restrict__ Wb,
           const float* __restrict__ Vw,  const float* __restrict__ Vb,
           float* __restrict__ out)
{
    extern __shared__ float sm[];
    const int tid = threadIdx.x;
    for (int i = tid; i < 300*100; i += DTHREADS){ int g=i/100,k=i%100; sm[D_WHH + k*300+g] = Whh[i]; }
    for (int i = tid; i < 300*11;  i += DTHREADS){ int g=i/11, v=i%11;  sm[D_WIH + v*300+g] = Wih[i]; }
    for (int i = tid; i < 11*100;  i += DTHREADS) sm[D_VW+i] = Vw[i];
    for (int i = tid; i < 300;     i += DTHREADS){ sm[D_BIH+i]=bih[i]; sm[D_BHH+i]=bhh[i]; }
    for (int i = tid; i < 100;     i += DTHREADS) sm[D_WB+i]=Wb[i];
    for (int i = tid; i < VDIM;    i += DTHREADS) sm[D_VB+i]=Vb[i];
    {   __half2* w2 = (__half2*)&sm[D_WW2];
        for (int i = tid; i < 200*50; i += DTHREADS){
            int k=i/50, p=i%50; int e0=2*p;
            w2[k*50+p] = __halves2half2(__float2half(Ww[e0*200+k]), __float2half(Ww[(e0+1)*200+k]));
        }
    }
    __syncthreads();

    const int warp = tid>>5, lane = tid&31;
    const int b = min(blockIdx.x*DWARPS + warp, BATCH-1);
    float* pc = &sm[D_PC + warp*800];
    float* sc = &sm[D_SC + warp*40];
    const __half2* w2 = (const __half2*)&sm[D_WW2];
    const bool hasB = (lane < 18);

    // init: h = H[:, t=9] into c-area, then P0 = GRU(SOS, h)
    #pragma unroll
    for (int m=0;m<4;m++){ int e=lane+32*m; if(e<HDIM){
        #pragma unroll
        for(int j=0;j<J;j++)
            pc[j*200+100+e] = g_H[(size_t)((b*J+j)*TIN + (TIN-1))*HDIM + e];
    } }
    __syncwarp();
    dec_gru(sm, pc, lane, VDIM-1);

    float score = 0.f;
    for (int t=0;t<TOUT;t++){
        // ---- A: scores[j][tt] = HA . P ----
        {
            int task = lane;
            int j = task/10, tt = task-10*j;
            const __half2* hap = (const __half2*)&g_HA[(size_t)((b*J+j)*TIN+tt)*HDIM];
            const float2*  pj  = (const float2*)&pc[j*200];
            float acc=0.f;
            #pragma unroll 10
            for (int q=0;q<50;q++){
                float2 hf=__half22float2(hap[q]); float2 pp=pj[q];
                acc = fmaf(hf.x,pp.x,acc); acc = fmaf(hf.y,pp.y,acc);
            }
            sc[task]=acc;
            if (lane<8){
                int task2=32+lane; int j2=task2/10, tt2=task2-10*j2;
                const __half2* hap2=(const __half2*)&g_HA[(size_t)((b*J+j2)*TIN+tt2)*HDIM];
                const float2*  pj2 =(const float2*)&pc[j2*200];
                float acc2=0.f;
                #pragma unroll 10
                for (int q=0;q<50;q++){
                    float2 hf=__half22float2(hap2[q]); float2 pp=pj2[q];
                    acc2 = fmaf(hf.x,pp.x,acc2); acc2 = fmaf(hf.y,pp.y,acc2);
                }
                sc[task2]=acc2;
            }
        }
        __syncwarp();
        // ---- B: log_softmax over tt (lanes 0..3) ----
        if (lane < J){
            float mx=-1e30f;
            #pragma unroll
            for(int tt=0;tt<TIN;tt++) mx=fmaxf(mx, sc[lane*10+tt]);
            float s=0.f;
            #pragma unroll
            for(int tt=0;tt<TIN;tt++) s+=__expf(sc[lane*10+tt]-mx);
            float lg=__logf(s)+mx;
            #pragma unroll
            for(int tt=0;tt<TIN;tt++) sc[lane*10+tt]-=lg;
        }
        __syncwarp();
        // ---- C: c[j] = sum_t logs * H ----
        float cacc[J][4];
        #pragma unroll
        for(int j=0;j<J;j++){
            #pragma unroll
            for(int m=0;m<4;m++) cacc[j][m]=0.f; }
        #pragma unroll
        for(int j=0;j<J;j++){
            #pragma unroll
            for(int tt=0;tt<TIN;tt++){
                float lg=sc[j*10+tt];
                const float* hp=&g_H[(size_t)((b*J+j)*TIN+tt)*HDIM];
                #pragma unroll
                for(int m=0;m<4;m++){ int e=lane+32*m; if(e<HDIM)
                    cacc[j][m]=fmaf(lg,hp[e],cacc[j][m]); }
            } }
        #pragma unroll
        for(int m=0;m<4;m++){ int e=lane+32*m; if(e<HDIM){
            #pragma unroll
            for(int j=0;j<J;j++) pc[j*200+100+e]=cacc[j][m]; } }
        __syncwarp();
        // ---- D: fc = tanh(W_w @ [P|c] + W_b), m = max_j ----
        float2 accA[J], accB[J];
        {
            float2 wbA = make_float2(sm[D_WB+2*lane], sm[D_WB+2*lane+1]);
            float2 wbB = hasB ? make_float2(sm[D_WB+64+2*lane], sm[D_WB+65+2*lane]) : make_float2(0.f,0.f);
            #pragma unroll
            for(int j=0;j<J;j++){ accA[j]=wbA; accB[j]=wbB; }
        }
        #pragma unroll 4
        for (int k=0;k<200;k++){
            float pa[J];
            #pragma unroll
            for(int j=0;j<J;j++) pa[j]=pc[j*200+k];
            float2 wA=__half22float2(w2[k*50+lane]);
            float2 wB = hasB ? __half22float2(w2[k*50+32+lane]) : make_float2(0.f,0.f);
            #pragma unroll
            for(int j=0;j<J;j++){
                accA[j].x=fmaf(wA.x,pa[j],accA[j].x);
                accA[j].y=fmaf(wA.y,pa[j],accA[j].y);
                accB[j].x=fmaf(wB.x,pa[j],accB[j].x);
                accB[j].y=fmaf(wB.y,pa[j],accB[j].y);
            }
        }
        float2 mA=make_float2(-1e30f,-1e30f), mB=make_float2(-1e30f,-1e30f);
        #pragma unroll
        for(int j=0;j<J;j++){
            mA.x=fmaxf(mA.x,tanhf(accA[j].x)); mA.y=fmaxf(mA.y,tanhf(accA[j].y));
            mB.x=fmaxf(mB.x,tanhf(accB[j].x)); mB.y=fmaxf(mB.y,tanhf(accB[j].y));
        }
        // ---- E: logits + log_softmax + score ----
        float pv[VDIM];
        #pragma unroll
        for(int v=0;v<VDIM;v++){
            const float* vr=&sm[D_VW+v*HDIM];
            float p = vr[2*lane]*mA.x + vr[2*lane+1]*mA.y;
            if (hasB){ p=fmaf(vr[64+2*lane],mB.x,p); p=fmaf(vr[65+2*lane],mB.y,p); }
            pv[v]=p;
        }
        #pragma unroll
        for (int off=16; off>=1; off>>=1){
            #pragma unroll
            for(int v=0;v<VDIM;v++) pv[v]+=__shfl_xor_sync(0xffffffffu,pv[v],off);
        }
        int tok = target[t*BATCH+b];
        float mx=-1e30f;
        #pragma unroll
        for(int v=0;v<VDIM;v++){ pv[v]+=sm[D_VB+v]; mx=fmaxf(mx,pv[v]); }
        float ssum=0.f;
        #pragma unroll
        for(int v=0;v<VDIM;v++) ssum+=__expf(pv[v]-mx);
        score += pv[tok]-mx-__logf(ssum);
        // ---- F: P = GRU(onehot(tok), c) ----
        dec_gru(sm, pc, lane, tok);
    }
    if (lane==0) out[b]=score;
}

// =================================================================
extern "C" void kernel_launch(void* const* d_in, const int* in_sizes, int n_in,
                              void* d_out, int out_size)
{
    const int*   inputs = (const int*)  d_in[0];
    const int*   target = (const int*)  d_in[1];
    const float* eWih   = (const float*)d_in[2];
    const float* eWhh   = (const float*)d_in[3];
    const float* ebih   = (const float*)d_in[4];
    const float* ebhh   = (const float*)d_in[5];
    const float* dWih   = (const float*)d_in[6];
    const float* dWhh   = (const float*)d_in[7];
    const float* dbih   = (const float*)d_in[8];
    const float* dbhh   = (const float*)d_in[9];
    const float* Ww     = (const float*)d_in[10];
    const float* Wb     = (const float*)d_in[11];
    const float* Vw     = (const float*)d_in[12];
    const float* Vb     = (const float*)d_in[13];
    const float* Aw     = (const float*)d_in[14];
    float* out = (float*)d_out;

    cudaFuncSetAttribute(enc_kernel, cudaFuncAttributeMaxDynamicSharedMemorySize, E_FLOATS*4);
    cudaFuncSetAttribute(dec_kernel, cudaFuncAttributeMaxDynamicSharedMemorySize, D_FLOATS*4);

    int egrid = (JB + ESEQB - 1)/ESEQB;      // 683
    int dgrid = (BATCH + DWARPS - 1)/DWARPS; // 683
    enc_kernel<<<egrid, ETHREADS, E_FLOATS*4>>>(inputs, eWih, eWhh, ebih, ebhh, Aw);
    dec_kernel<<<dgrid, DTHREADS, D_FLOATS*4>>>(target, dWih, dWhh, dbih, dbhh,
                                                Ww, Wb, Vw, Vb, out);
}

// round 3
// speedup vs baseline: 1.1047x; 1.1047x over previous
#include <cuda_runtime.h>
#include <cuda_fp16.h>
#include <math.h>
#include <cstdint>

#define J 4
#define BATCH 8192
#define TIN 10
#define TOUT 10
#define HDIM 100
#define VDIM 11
#define JB (J*BATCH)

#define NWARP 12
#define NTHREADS (NWARP*32)

typedef unsigned long long u64;

// ---------------- global scratch (allocation-free) ----------------
__device__ float g_H [(size_t)JB*TIN*HDIM];   // [b][j][t][e]
__device__ float g_HA[(size_t)JB*TIN*HDIM];   // [b][j][t][f]

// ---------------- packed f32x2 helpers ----------------
__device__ __forceinline__ void fma2(u64 &d, u64 a, u64 b){
    asm("fma.rn.f32x2 %0, %1, %2, %0;" : "+l"(d) : "l"(a), "l"(b));
}
__device__ __forceinline__ u64 dup2(float x){
    u64 r; asm("mov.b64 %0, {%1, %1};" : "=l"(r) : "f"(x)); return r;
}
__device__ __forceinline__ u64 pack2(float x, float y){
    u64 r; asm("mov.b64 %0, {%1, %2};" : "=l"(r) : "f"(x), "f"(y)); return r;
}
__device__ __forceinline__ float2 unpack2(u64 v){
    float2 f; asm("mov.b64 {%0, %1}, %2;" : "=f"(f.x), "=f"(f.y) : "l"(v)); return f;
}
__device__ __forceinline__ float sigm(float x){ return __fdividef(1.f, 1.f+__expf(-x)); }
__device__ __forceinline__ float tanh_f(float x){
    return fmaf(2.f, __fdividef(1.f, 1.f+__expf(-2.f*x)), -1.f);
}

// ---------------- shared memory layout (float offsets) ----------------
// encoder phase
#define E_WHH 0        // WhhT [100][300]
#define E_WIH 30000    // WihT [11][300]
#define E_AW  33300    // A_w  [100][100]
#define E_BIH 43300
#define E_BHH 43600
#define E_H   43900    // h [12][4][100]
// decoder phase (reuses same smem after __syncthreads)
#define D_WHH 0        // WhhT [100][300]
#define D_WIH 30000    // WihT [11][300]
#define D_VW  33300    // V_w [11][100]
#define D_BIH 34400
#define D_BHH 34700
#define D_WB  35000
#define D_VB  35100    // 12 slots (pad)
#define D_PC  35112    // [12][4][200]  P|c
#define D_SC  44712    // [12][40]
#define D_WW2 45192    // half2 [200][50]
#define SM_FLOATS 55192  // 220768 bytes

// =================================================================
// packed decoder GRU: P[j] = GRU(onehot(tok), c[j]); c in pc[+100], P out pc[+0]
// =================================================================
__device__ __forceinline__ void dec_gru(const float* __restrict__ sm,
                                        float* __restrict__ pc,
                                        int lane, int tok)
{
    const int e0 = 2*lane, e1 = 64 + 2*lane;
    const bool m1 = (lane < 18);
    u64 gr[J][2], gz[J][2], gn[J][2];
    {
        u64 br0=*(const u64*)&sm[D_BHH+e0], bz0=*(const u64*)&sm[D_BHH+100+e0], bn0=*(const u64*)&sm[D_BHH+200+e0];
        u64 br1=0, bz1=0, bn1=0;
        if (m1){ br1=*(const u64*)&sm[D_BHH+e1]; bz1=*(const u64*)&sm[D_BHH+100+e1]; bn1=*(const u64*)&sm[D_BHH+200+e1]; }
        #pragma unroll
        for(int j=0;j<J;j++){ gr[j][0]=br0; gz[j][0]=bz0; gn[j][0]=bn0;
                              gr[j][1]=br1; gz[j][1]=bz1; gn[j][1]=bn1; }
    }
    #pragma unroll 2
    for (int k=0;k<HDIM;k+=2){
        float2 cc[J];
        #pragma unroll
        for(int j=0;j<J;j++) cc[j] = *(const float2*)&pc[j*200+100+k];
        #pragma unroll
        for (int s=0;s<2;s++){
            const float* wrow = &sm[D_WHH + (k+s)*300];
            u64 cb[J];
            #pragma unroll
            for(int j=0;j<J;j++) cb[j] = dup2(s? cc[j].y : cc[j].x);
            u64 wr0=*(const u64*)(wrow+e0), wz0=*(const u64*)(wrow+100+e0), wn0=*(const u64*)(wrow+200+e0);
            #pragma unroll
            for(int j=0;j<J;j++){ fma2(gr[j][0],wr0,cb[j]); fma2(gz[j][0],wz0,cb[j]); fma2(gn[j][0],wn0,cb[j]); }
            if (m1){
                u64 wr1=*(const u64*)(wrow+e1), wz1=*(const u64*)(wrow+100+e1), wn1=*(const u64*)(wrow+200+e1);
                #pragma unroll
                for(int j=0;j<J;j++){ fma2(gr[j][1],wr1,cb[j]); fma2(gz[j][1],wz1,cb[j]); fma2(gn[j][1],wn1,cb[j]); }
            }
        }
    }
    const float* wi = &sm[D_WIH + tok*300];
    #pragma unroll
    for (int m=0;m<2;m++){
        if (m==1 && !m1) break;
        const int e = m? e1 : e0;
        float2 b_r=*(const float2*)&sm[D_BIH+e];
        float2 b_z=*(const float2*)&sm[D_BIH+100+e];
        float2 b_n=*(const float2*)&sm[D_BIH+200+e];
        float2 wir=*(const float2*)&wi[e], wiz=*(const float2*)&wi[100+e], win=*(const float2*)&wi[200+e];
        float ir0=wir.x+b_r.x, ir1=wir.y+b_r.y;
        float iz0=wiz.x+b_z.x, iz1=wiz.y+b_z.y;
        float in0=win.x+b_n.x, in1=win.y+b_n.y;
        #pragma unroll
        for(int j=0;j<J;j++){
            float2 R=unpack2(gr[j][m]), Z=unpack2(gz[j][m]), N=unpack2(gn[j][m]);
            float2 cj=*(const float2*)&pc[j*200+100+e];
            float r0=sigm(ir0+R.x), z0=sigm(iz0+Z.x);
            float n0=tanh_f(in0 + r0*N.x);
            float r1=sigm(ir1+R.y), z1=sigm(iz1+Z.y);
            float n1=tanh_f(in1 + r1*N.y);
            float2 pn; pn.x=(1.f-z0)*n0 + z0*cj.x; pn.y=(1.f-z1)*n1 + z1*cj.y;
            *(float2*)&pc[j*200+e] = pn;
        }
    }
    __syncwarp();
}

// =================================================================
__global__ void __launch_bounds__(NTHREADS,1)
fused_kernel(const int* __restrict__ inputs, const int* __restrict__ target,
             const float* __restrict__ eWih, const float* __restrict__ eWhh,
             const float* __restrict__ ebih, const float* __restrict__ ebhh,
             const float* __restrict__ dWih, const float* __restrict__ dWhh,
             const float* __restrict__ dbih, const float* __restrict__ dbhh,
             const float* __restrict__ Ww,  const float* __restrict__ Wb,
             const float* __restrict__ Vw,  const float* __restrict__ Vb,
             const float* __restrict__ Aw,  float* __restrict__ out)
{
    extern __shared__ float sm[];
    const int tid = threadIdx.x;
    const int warp = tid>>5, lane = tid&31;
    const int b = min(blockIdx.x*NWARP + warp, BATCH-1);
    const int e0 = 2*lane, e1 = 64 + 2*lane;
    const bool m1 = (lane < 18);

    // ================= ENCODER PHASE =================
    for (int i=tid;i<300*100;i+=NTHREADS){ int g=i/100,k=i%100; sm[E_WHH+k*300+g]=eWhh[i]; }
    for (int i=tid;i<300*11; i+=NTHREADS){ int g=i/11, v=i%11;  sm[E_WIH+v*300+g]=eWih[i]; }
    for (int i=tid;i<100*100;i+=NTHREADS) sm[E_AW+i]=Aw[i];
    for (int i=tid;i<300;    i+=NTHREADS){ sm[E_BIH+i]=ebih[i]; sm[E_BHH+i]=ebhh[i]; }
    __syncthreads();

    {
        float* hrow[J];
        #pragma unroll
        for(int j=0;j<J;j++) hrow[j]=&sm[E_H + (warp*J+j)*HDIM];
        float2 z2; z2.x=0.f; z2.y=0.f;
        #pragma unroll
        for(int j=0;j<J;j++){ *(float2*)&hrow[j][e0]=z2; if(m1) *(float2*)&hrow[j][e1]=z2; }
        __syncwarp();

        #pragma unroll 1
        for (int t=0;t<TIN;t++){
            int tok[J];
            #pragma unroll
            for(int j=0;j<J;j++) tok[j]=inputs[(j*TIN+t)*BATCH + b];

            u64 ar[J][2], az[J][2], an[J][2];
            {
                u64 br0=*(const u64*)&sm[E_BHH+e0], bz0=*(const u64*)&sm[E_BHH+100+e0], bn0=*(const u64*)&sm[E_BHH+200+e0];
                u64 br1=0,bz1=0,bn1=0;
                if(m1){ br1=*(const u64*)&sm[E_BHH+e1]; bz1=*(const u64*)&sm[E_BHH+100+e1]; bn1=*(const u64*)&sm[E_BHH+200+e1]; }
                #pragma unroll
                for(int j=0;j<J;j++){ ar[j][0]=br0; az[j][0]=bz0; an[j][0]=bn0;
                                      ar[j][1]=br1; az[j][1]=bz1; an[j][1]=bn1; }
            }
            if (t>0){   // at t==0, h==0 -> Whh@h == 0
                #pragma unroll 2
                for (int k=0;k<HDIM;k+=2){
                    float2 hk[J];
                    #pragma unroll
                    for(int j=0;j<J;j++) hk[j]=*(const float2*)&hrow[j][k];
                    #pragma unroll
                    for (int s=0;s<2;s++){
                        const float* wrow=&sm[E_WHH+(k+s)*300];
                        u64 hb[J];
                        #pragma unroll
                        for(int j=0;j<J;j++) hb[j]=dup2(s?hk[j].y:hk[j].x);
                        u64 wr0=*(const u64*)(wrow+e0), wz0=*(const u64*)(wrow+100+e0), wn0=*(const u64*)(wrow+200+e0);
                        #pragma unroll
                        for(int j=0;j<J;j++){ fma2(ar[j][0],wr0,hb[j]); fma2(az[j][0],wz0,hb[j]); fma2(an[j][0],wn0,hb[j]); }
                        if(m1){
                            u64 wr1=*(const u64*)(wrow+e1), wz1=*(const u64*)(wrow+100+e1), wn1=*(const u64*)(wrow+200+e1);
                            #pragma unroll
                            for(int j=0;j<J;j++){ fma2(ar[j][1],wr1,hb[j]); fma2(az[j][1],wz1,hb[j]); fma2(an[j][1],wn1,hb[j]); }
                        }
                    }
                }
            }
            // gates + h update + store H
            #pragma unroll
            for (int m=0;m<2;m++){
                if (m==1 && !m1) break;
                const int e = m? e1 : e0;
                float2 b_r=*(const float2*)&sm[E_BIH+e];
                float2 b_z=*(const float2*)&sm[E_BIH+100+e];
                float2 b_n=*(const float2*)&sm[E_BIH+200+e];
                #pragma unroll
                for(int j=0;j<J;j++){
                    const float* wi=&sm[E_WIH+tok[j]*300];
                    float2 wir=*(const float2*)&wi[e], wiz=*(const float2*)&wi[100+e], win=*(const float2*)&wi[200+e];
                    float2 R=unpack2(ar[j][m]), Z=unpack2(az[j][m]), N=unpack2(an[j][m]);
                    float2 ho=*(const float2*)&hrow[j][e];
                    float r0=sigm(wir.x+b_r.x+R.x), z0=sigm(wiz.x+b_z.x+Z.x);
                    float n0=tanh_f(win.x+b_n.x + r0*N.x);
                    float r1=sigm(wir.y+b_r.y+R.y), z1=sigm(wiz.y+b_z.y+Z.y);
                    float n1=tanh_f(win.y+b_n.y + r1*N.y);
                    float2 hn; hn.x=(1.f-z0)*n0+z0*ho.x; hn.y=(1.f-z1)*n1+z1*ho.y;
                    *(float2*)&hrow[j][e]=hn;
                    *(float2*)&g_H[((size_t)(b*J+j)*TIN+t)*HDIM + e]=hn;
                }
            }
            __syncwarp();
            // HA = h @ A_w
            u64 ha[J][2];
            #pragma unroll
            for(int j=0;j<J;j++){ ha[j][0]=0ull; ha[j][1]=0ull; }
            #pragma unroll 2
            for (int e=0;e<HDIM;e+=2){
                float2 he[J];
                #pragma unroll
                for(int j=0;j<J;j++) he[j]=*(const float2*)&hrow[j][e];
                #pragma unroll
                for (int s=0;s<2;s++){
                    const float* arow=&sm[E_AW+(e+s)*100];
                    u64 hb[J];
                    #pragma unroll
                    for(int j=0;j<J;j++) hb[j]=dup2(s?he[j].y:he[j].x);
                    u64 a0=*(const u64*)(arow+e0);
                    #pragma unroll
                    for(int j=0;j<J;j++) fma2(ha[j][0],a0,hb[j]);
                    if(m1){
                        u64 a1=*(const u64*)(arow+e1);
                        #pragma unroll
                        for(int j=0;j<J;j++) fma2(ha[j][1],a1,hb[j]);
                    }
                }
            }
            #pragma unroll
            for(int j=0;j<J;j++){
                *(float2*)&g_HA[((size_t)(b*J+j)*TIN+t)*HDIM + e0]=unpack2(ha[j][0]);
                if(m1) *(float2*)&g_HA[((size_t)(b*J+j)*TIN+t)*HDIM + e1]=unpack2(ha[j][1]);
            }
            __syncwarp();
        }
    }
    __syncthreads();

    // ================= DECODER PHASE =================
    for (int i=tid;i<300*100;i+=NTHREADS){ int g=i/100,k=i%100; sm[D_WHH+k*300+g]=dWhh[i]; }
    for (int i=tid;i<300*11; i+=NTHREADS){ int g=i/11, v=i%11;  sm[D_WIH+v*300+g]=dWih[i]; }
    for (int i=tid;i<11*100; i+=NTHREADS) sm[D_VW+i]=Vw[i];
    for (int i=tid;i<300;    i+=NTHREADS){ sm[D_BIH+i]=dbih[i]; sm[D_BHH+i]=dbhh[i]; }
    for (int i=tid;i<100;    i+=NTHREADS) sm[D_WB+i]=Wb[i];
    for (int i=tid;i<VDIM;   i+=NTHREADS) sm[D_VB+i]=Vb[i];
    {
        __half2* w2=(__half2*)&sm[D_WW2];
        for (int i=tid;i<200*50;i+=NTHREADS){
            int k=i/50, p=i%50; int ee=2*p;
            w2[k*50+p]=__halves2half2(__float2half(Ww[ee*200+k]), __float2half(Ww[(ee+1)*200+k]));
        }
    }
    __syncthreads();

    float* pc=&sm[D_PC + warp*800];
    float* sc=&sm[D_SC + warp*40];
    const __half2* w2=(const __half2*)&sm[D_WW2];

    // init: c = H[:, t=9]; P0 = GRU(SOS, c)
    #pragma unroll
    for(int j=0;j<J;j++){
        *(float2*)&pc[j*200+100+e0]=*(const float2*)&g_H[((size_t)(b*J+j)*TIN+(TIN-1))*HDIM+e0];
        if(m1) *(float2*)&pc[j*200+100+e1]=*(const float2*)&g_H[((size_t)(b*J+j)*TIN+(TIN-1))*HDIM+e1];
    }
    __syncwarp();
    dec_gru(sm, pc, lane, VDIM-1);

    float score=0.f;
    #pragma unroll 1
    for (int t=0;t<TOUT;t++){
        // ---- A: scores[j][tt] = HA[j][tt] . P[j] ----
        {
            int j=lane/10, tt=lane-10*j;
            const u64* hap=(const u64*)&g_HA[((size_t)(b*J+j)*TIN+tt)*HDIM];
            const u64* pj =(const u64*)&pc[j*200];
            u64 acc=0ull;
            #pragma unroll 10
            for(int q=0;q<50;q++) fma2(acc,hap[q],pj[q]);
            float2 f=unpack2(acc); sc[lane]=f.x+f.y;
            if (lane<8){
                int t2=32+lane; int j2=t2/10, tt2=t2-10*j2;
                const u64* hap2=(const u64*)&g_HA[((size_t)(b*J+j2)*TIN+tt2)*HDIM];
                const u64* pj2 =(const u64*)&pc[j2*200];
                u64 acc2=0ull;
                #pragma unroll 10
                for(int q=0;q<50;q++) fma2(acc2,hap2[q],pj2[q]);
                float2 f2=unpack2(acc2); sc[t2]=f2.x+f2.y;
            }
        }
        __syncwarp();
        // ---- B: log_softmax over tt ----
        if (lane<J){
            float mx=-1e30f;
            #pragma unroll
            for(int tt=0;tt<TIN;tt++) mx=fmaxf(mx,sc[lane*10+tt]);
            float s=0.f;
            #pragma unroll
            for(int tt=0;tt<TIN;tt++) s+=__expf(sc[lane*10+tt]-mx);
            float lg=__logf(s)+mx;
            #pragma unroll
            for(int tt=0;tt<TIN;tt++) sc[lane*10+tt]-=lg;
        }
        __syncwarp();
        // ---- C: c[j] = sum_tt logs * H ----
        {
            u64 cacc[J][2];
            #pragma unroll
            for(int j=0;j<J;j++){ cacc[j][0]=0ull; cacc[j][1]=0ull; }
            #pragma unroll
            for(int j=0;j<J;j++){
                const float* hb=&g_H[((size_t)(b*J+j)*TIN)*HDIM];
                #pragma unroll
                for(int tt=0;tt<TIN;tt++){
                    u64 lg2=dup2(sc[j*10+tt]);
                    const float* hp=hb+tt*HDIM;
                    fma2(cacc[j][0], *(const u64*)(hp+e0), lg2);
                    if(m1) fma2(cacc[j][1], *(const u64*)(hp+e1), lg2);
                }
            }
            #pragma unroll
            for(int j=0;j<J;j++){
                *(float2*)&pc[j*200+100+e0]=unpack2(cacc[j][0]);
                if(m1) *(float2*)&pc[j*200+100+e1]=unpack2(cacc[j][1]);
            }
        }
        __syncwarp();
        // ---- D: fc = tanh(W_w @ [P|c] + W_b), max over j ----
        u64 accA[J], accB[J];
        {
            float2 wbA=*(const float2*)&sm[D_WB+e0];
            u64 a0=pack2(wbA.x,wbA.y);
            u64 b0=0ull;
            if(m1){ float2 wbB=*(const float2*)&sm[D_WB+e1]; b0=pack2(wbB.x,wbB.y); }
            #pragma unroll
            for(int j=0;j<J;j++){ accA[j]=a0; accB[j]=b0; }
        }
        #pragma unroll 2
        for (int k=0;k<200;k+=2){
            float2 pa[J];
            #pragma unroll
            for(int j=0;j<J;j++) pa[j]=*(const float2*)&pc[j*200+k];
            #pragma unroll
            for (int s=0;s<2;s++){
                int kk=k+s;
                float2 wAf=__half22float2(w2[kk*50+lane]);
                u64 wA=pack2(wAf.x,wAf.y);
                u64 pb[J];
                #pragma unroll
                for(int j=0;j<J;j++) pb[j]=dup2(s?pa[j].y:pa[j].x);
                #pragma unroll
                for(int j=0;j<J;j++) fma2(accA[j],wA,pb[j]);
                if(m1){
                    float2 wBf=__half22float2(w2[kk*50+32+lane]);
                    u64 wB=pack2(wBf.x,wBf.y);
                    #pragma unroll
                    for(int j=0;j<J;j++) fma2(accB[j],wB,pb[j]);
                }
            }
        }
        float2 mA; mA.x=-1e30f; mA.y=-1e30f;
        float2 mB=mA;
        #pragma unroll
        for(int j=0;j<J;j++){
            float2 fA=unpack2(accA[j]);
            mA.x=fmaxf(mA.x,tanh_f(fA.x)); mA.y=fmaxf(mA.y,tanh_f(fA.y));
            if(m1){ float2 fB=unpack2(accB[j]);
                mB.x=fmaxf(mB.x,tanh_f(fB.x)); mB.y=fmaxf(mB.y,tanh_f(fB.y)); }
        }
        // ---- E: logits + log_softmax + score ----
        float pv[VDIM];
        #pragma unroll
        for(int v=0;v<VDIM;v++){
            const float* vr=&sm[D_VW+v*HDIM];
            float2 vA=*(const float2*)&vr[e0];
            float p=vA.x*mA.x + vA.y*mA.y;
            if(m1){ float2 vB=*(const float2*)&vr[e1]; p=fmaf(vB.x,mB.x,p); p=fmaf(vB.y,mB.y,p); }
            pv[v]=p;
        }
        #pragma unroll
        for (int off=16; off>=1; off>>=1){
            #pragma unroll
            for(int v=0;v<VDIM;v++) pv[v]+=__shfl_xor_sync(0xffffffffu,pv[v],off);
        }
        int tok=target[t*BATCH+b];
        float mx=-1e30f;
        #pragma unroll
        for(int v=0;v<VDIM;v++){ pv[v]+=sm[D_VB+v]; mx=fmaxf(mx,pv[v]); }
        float ssum=0.f;
        #pragma unroll
        for(int v=0;v<VDIM;v++) ssum+=__expf(pv[v]-mx);
        score += pv[tok]-mx-__logf(ssum);
        // ---- F: P = GRU(onehot(tok), c) ----
        dec_gru(sm, pc, lane, tok);
    }
    if (lane==0) out[b]=score;
}

// =================================================================
extern "C" void kernel_launch(void* const* d_in, const int* in_sizes, int n_in,
                              void* d_out, int out_size)
{
    const int*   inputs = (const int*)  d_in[0];
    const int*   target = (const int*)  d_in[1];
    const float* eWih   = (const float*)d_in[2];
    const float* eWhh   = (const float*)d_in[3];
    const float* ebih   = (const float*)d_in[4];
    const float* ebhh   = (const float*)d_in[5];
    const float* dWih   = (const float*)d_in[6];
    const float* dWhh   = (const float*)d_in[7];
    const float* dbih   = (const float*)d_in[8];
    const float* dbhh   = (const float*)d_in[9];
    const float* Ww     = (const float*)d_in[10];
    const float* Wb     = (const float*)d_in[11];
    const float* Vw     = (const float*)d_in[12];
    const float* Vb     = (const float*)d_in[13];
    const float* Aw     = (const float*)d_in[14];
    float* out = (float*)d_out;

    cudaFuncSetAttribute(fused_kernel, cudaFuncAttributeMaxDynamicSharedMemorySize, SM_FLOATS*4);
    int grid = (BATCH + NWARP - 1)/NWARP;  // 683
    fused_kernel<<<grid, NTHREADS, SM_FLOATS*4>>>(inputs, target,
        eWih, eWhh, ebih, ebhh, dWih, dWhh, dbih, dbhh,
        Ww, Wb, Vw, Vb, Aw, out);
}